// round 6
// baseline (speedup 1.0000x reference)
#include <cuda_runtime.h>
#include <cuda_fp16.h>
#include <math.h>
#include <cstdint>

// Problem constants
#define Bc   2
#define Sc   2048
#define HIDc 2048
#define Hc   16
#define HKVc 4
#define Dc   128
#define BSc  64
#define NBc  32
#define SCALEc 0.08838834764831845f   // 1/sqrt(128)

// ---------------- scratch (device globals; no allocation allowed) ----------------
__device__ float    g_qkv[(size_t)4096 * 3072];          // hidden @ [Wq|Wk|Wv]
__device__ float    g_qblk[Bc * Hc   * NBc * Dc];
__device__ float    g_kblk[Bc * HKVc * NBc * Dc];
__device__ unsigned g_mask[Bc * Hc * NBc];               // bit j of row i: block (i,j) active

// fp16 limb arrays (value = hi + lo)
__device__ __half g_hh [(size_t)4096 * 2048];   // hidden hi
__device__ __half g_hl [(size_t)4096 * 2048];   // hidden lo
__device__ __half g_wth[(size_t)3072 * 2048];   // [Wq^T;Wk^T;Wv^T] hi  (rows=N, cols=K)
__device__ __half g_wtl[(size_t)3072 * 2048];
__device__ __half g_woth[(size_t)2048 * 2048];  // Wo^T hi
__device__ __half g_wotl[(size_t)2048 * 2048];
__device__ __half g_ath[(size_t)4096 * 2048];   // attn out hi (B,S,H*D)
__device__ __half g_atl[(size_t)4096 * 2048];
// roped q/k and v limbs
__device__ __half g_qh[(size_t)Bc * Hc   * Sc * Dc];
__device__ __half g_ql[(size_t)Bc * Hc   * Sc * Dc];
__device__ __half g_kh[(size_t)Bc * HKVc * Sc * Dc];
__device__ __half g_kl[(size_t)Bc * HKVc * Sc * Dc];
__device__ __half g_vh[(size_t)Bc * HKVc * Sc * Dc];
__device__ __half g_vl[(size_t)Bc * HKVc * Sc * Dc];

// ======================= helpers =======================
__device__ __forceinline__ uint32_t smem_u32(const void* p) {
    uint32_t a;
    asm("{ .reg .u64 t; cvta.to.shared.u64 t, %1; cvt.u32.u64 %0, t; }" : "=r"(a) : "l"(p));
    return a;
}
__device__ __forceinline__ void ldm4(uint32_t addr, uint32_t* r) {
    asm volatile("ldmatrix.sync.aligned.m8n8.x4.shared.b16 {%0,%1,%2,%3}, [%4];"
        : "=r"(r[0]), "=r"(r[1]), "=r"(r[2]), "=r"(r[3]) : "r"(addr));
}
__device__ __forceinline__ void ldm4t(uint32_t addr, uint32_t* r) {
    asm volatile("ldmatrix.sync.aligned.m8n8.x4.trans.shared.b16 {%0,%1,%2,%3}, [%4];"
        : "=r"(r[0]), "=r"(r[1]), "=r"(r[2]), "=r"(r[3]) : "r"(addr));
}
#define MMA_F16(d, a, b) \
    asm volatile("mma.sync.aligned.m16n8k16.row.col.f32.f16.f16.f32 " \
        "{%0,%1,%2,%3}, {%4,%5,%6,%7}, {%8,%9}, {%0,%1,%2,%3};" \
        : "+f"((d)[0]), "+f"((d)[1]), "+f"((d)[2]), "+f"((d)[3]) \
        : "r"((a)[0]), "r"((a)[1]), "r"((a)[2]), "r"((a)[3]), \
          "r"((b)[0]), "r"((b)[1]))
#define CP_ASYNC16(dst, src) \
    asm volatile("cp.async.cg.shared.global [%0], [%1], 16;" :: "r"(dst), "l"(src))
#define CP_COMMIT()  asm volatile("cp.async.commit_group;" ::: "memory")
#define CP_WAIT1()   asm volatile("cp.async.wait_group 1;" ::: "memory")
#define CP_WAIT0()   asm volatile("cp.async.wait_group 0;" ::: "memory")

__device__ __forceinline__ void wsplit(__half* ph, __half* pl, size_t i, float v) {
    __half h = __float2half_rn(v);
    ph[i] = h;
    pl[i] = __float2half_rn(v - __half2float(h));
}
__device__ __forceinline__ uint32_t packh2(float x, float y) {
    __half2 h = __floats2half2_rn(x, y);
    return *(uint32_t*)&h;
}

// ================== fp16x3 split GEMM: C[M,*] = (A) @ (Bt)^T ==================
#define KCH     32
#define TROW    40                         // halfs per smem row
#define TILE_B  (128 * TROW * 2)           // 10240 B
#define STAGE_B (4 * TILE_B)               // 40960 B
#define GEMM_SMEM (2 * STAGE_B)            // 81920 B

__global__ void __launch_bounds__(256, 2) gemm_h(
    const __half* __restrict__ Ahg, const __half* __restrict__ Alg,
    const __half* __restrict__ Bhg, const __half* __restrict__ Blg,
    float* __restrict__ C, int ldc, int K)
{
    extern __shared__ char smc[];
    const uint32_t sb = smem_u32(smc);
    const int tid = threadIdx.x;
    const int wid = tid >> 5, lane = tid & 31;
    const int wm = wid & 1, wn = wid >> 1;
    const int g = lane >> 2, q = lane & 3;
    const int row0 = blockIdx.y * 128;
    const int col0 = blockIdx.x * 128;
    const __half* A0 = Ahg + (size_t)row0 * K;
    const __half* A1 = Alg + (size_t)row0 * K;
    const __half* B0 = Bhg + (size_t)col0 * K;
    const __half* B1 = Blg + (size_t)col0 * K;

    float acc[4][4][4];
#pragma unroll
    for (int t = 0; t < 4; t++)
#pragma unroll
        for (int u = 0; u < 4; u++)
#pragma unroll
            for (int r = 0; r < 4; r++) acc[t][u][r] = 0.f;

    const int lrow = lane & 15;
    const uint32_t lk = (uint32_t)(lane >> 4) * 16;

    auto prefetch = [&](int kc, int s) {
        const int k0 = kc * KCH;
        const uint32_t st = sb + s * STAGE_B;
        const __half* gs[4] = {A0, A1, B0, B1};
#pragma unroll
        for (int t4 = 0; t4 < 4; t4++) {
#pragma unroll
            for (int j = 0; j < 2; j++) {
                int idx = tid + j * 256;
                int row = idx >> 2, seg = idx & 3;
                uint32_t dst = st + t4 * TILE_B + row * 80 + seg * 16;
                const __half* src = gs[t4] + (size_t)row * K + k0 + seg * 8;
                CP_ASYNC16(dst, src);
            }
        }
    };

    auto compute = [&](int s) {
        const uint32_t st = sb + s * STAGE_B;
#pragma unroll
        for (int kb = 0; kb < 2; kb++) {
            const uint32_t ko = kb * 32 + lk;
            uint32_t a[4][4], b[4][2], b2[4][2], r[4];
#pragma unroll
            for (int p = 0; p < 2; p++) {
                ldm4(st + 2 * TILE_B + (wn * 32 + p * 16 + lrow) * 80 + ko, r);
                b[2 * p][0] = r[0]; b[2 * p + 1][0] = r[1];
                b[2 * p][1] = r[2]; b[2 * p + 1][1] = r[3];
            }
#pragma unroll
            for (int t = 0; t < 4; t++)
                ldm4(st + (wm * 64 + t * 16 + lrow) * 80 + ko, a[t]);
#pragma unroll
            for (int t = 0; t < 4; t++)
#pragma unroll
                for (int u = 0; u < 4; u++) MMA_F16(acc[t][u], a[t], b[u]);
#pragma unroll
            for (int p = 0; p < 2; p++) {
                ldm4(st + 3 * TILE_B + (wn * 32 + p * 16 + lrow) * 80 + ko, r);
                b2[2 * p][0] = r[0]; b2[2 * p + 1][0] = r[1];
                b2[2 * p][1] = r[2]; b2[2 * p + 1][1] = r[3];
            }
#pragma unroll
            for (int t = 0; t < 4; t++)
#pragma unroll
                for (int u = 0; u < 4; u++) MMA_F16(acc[t][u], a[t], b2[u]);
#pragma unroll
            for (int t = 0; t < 4; t++)
                ldm4(st + TILE_B + (wm * 64 + t * 16 + lrow) * 80 + ko, a[t]);
#pragma unroll
            for (int t = 0; t < 4; t++)
#pragma unroll
                for (int u = 0; u < 4; u++) MMA_F16(acc[t][u], a[t], b[u]);
        }
    };

    const int nch = K / KCH;
    prefetch(0, 0); CP_COMMIT();
    prefetch(1, 1); CP_COMMIT();
    for (int kc = 0; kc < nch; kc++) {
        int s = kc & 1;
        if (kc + 1 < nch) { CP_WAIT1(); } else { CP_WAIT0(); }
        __syncthreads();
        compute(s);
        __syncthreads();
        if (kc + 2 < nch) prefetch(kc + 2, s);
        CP_COMMIT();
    }

#pragma unroll
    for (int t = 0; t < 4; t++) {
        int r = row0 + wm * 64 + t * 16 + g;
#pragma unroll
        for (int u = 0; u < 4; u++) {
            int c = col0 + wn * 32 + u * 8 + q * 2;
            *(float2*)(C + (size_t)r * ldc + c)       = make_float2(acc[t][u][0], acc[t][u][1]);
            *(float2*)(C + (size_t)(r + 8) * ldc + c) = make_float2(acc[t][u][2], acc[t][u][3]);
        }
    }
}

// ---------------- transpose + fp16 limb split ----------------
__global__ __launch_bounds__(256) void transpose_split(
    const float* __restrict__ in, __half* __restrict__ oh, __half* __restrict__ ol,
    int Kdim, int Ndim)
{
    __shared__ float t[32][33];
    int bx = blockIdx.x * 32, by = blockIdx.y * 32;
    int x = threadIdx.x, y = threadIdx.y;
#pragma unroll
    for (int i = 0; i < 32; i += 8)
        t[y + i][x] = in[(size_t)(by + y + i) * Ndim + bx + x];
    __syncthreads();
#pragma unroll
    for (int i = 0; i < 32; i += 8)
        wsplit(oh, ol, (size_t)(bx + y + i) * Kdim + by + x, t[x][y + i]);
}

// ---------------- fp16 limb split (no transpose) ----------------
__global__ __launch_bounds__(256) void split_kernel(
    const float* __restrict__ in, __half* __restrict__ oh, __half* __restrict__ ol, int n)
{
    int i = (blockIdx.x * 256 + threadIdx.x) * 4;
    if (i >= n) return;
    float4 v = *(const float4*)(in + i);
    wsplit(oh, ol, i,     v.x);
    wsplit(oh, ol, i + 1, v.y);
    wsplit(oh, ol, i + 2, v.z);
    wsplit(oh, ol, i + 3, v.w);
}

// ---------------- RoPE + reshape -> fp16 limbs ----------------
__global__ void rope_h(const float* __restrict__ qkv,
                       const float* __restrict__ cosb,
                       const float* __restrict__ sinb)
{
    int s = blockIdx.x, b = blockIdx.y;
    const float* row = qkv + (size_t)(b * Sc + s) * 3072;
    const float* cr  = cosb + (size_t)(b * Sc + s) * Dc;
    const float* sr  = sinb + (size_t)(b * Sc + s) * Dc;
    int t = threadIdx.x;

    for (int p = t; p < Hc * 64; p += 256) {            // q pairs
        int h = p >> 6, d = p & 63;
        float x1 = row[h * 128 + d], x2 = row[h * 128 + d + 64];
        size_t base = ((size_t)(b * Hc + h) * Sc + s) * Dc;
        wsplit(g_qh, g_ql, base + d,      x1 * cr[d]      - x2 * sr[d]);
        wsplit(g_qh, g_ql, base + d + 64, x2 * cr[d + 64] + x1 * sr[d + 64]);
    }
    for (int p = t; p < HKVc * 64; p += 256) {          // k pairs
        int h = p >> 6, d = p & 63;
        float x1 = row[2048 + h * 128 + d], x2 = row[2048 + h * 128 + d + 64];
        size_t base = ((size_t)(b * HKVc + h) * Sc + s) * Dc;
        wsplit(g_kh, g_kl, base + d,      x1 * cr[d]      - x2 * sr[d]);
        wsplit(g_kh, g_kl, base + d + 64, x2 * cr[d + 64] + x1 * sr[d + 64]);
    }
    for (int p = t; p < HKVc * Dc; p += 256) {          // v
        int h = p >> 7, d = p & 127;
        size_t base = ((size_t)(b * HKVc + h) * Sc + s) * Dc;
        wsplit(g_vh, g_vl, base + d, row[2560 + h * 128 + d]);
    }
}

// ---------------- block means over BS=64 rows (from limbs) ----------------
__global__ void blockmean_h(const __half* __restrict__ xh, const __half* __restrict__ xl,
                            float* __restrict__ out, int HH)
{
    int i = blockIdx.x, h = blockIdx.y, b = blockIdx.z, d = threadIdx.x;
    size_t base = ((size_t)(b * HH + h) * Sc + i * BSc) * Dc + d;
    float sum = 0.f;
#pragma unroll
    for (int r = 0; r < BSc; r++) {
        size_t idx = base + (size_t)r * Dc;
        sum += __half2float(xh[idx]) + __half2float(xl[idx]);
    }
    out[((size_t)(b * HH + h) * NBc + i) * Dc + d] = sum * (1.0f / 64.0f);
}

// ---------------- gate mask ----------------
__global__ __launch_bounds__(1024) void mask_kernel()
{
    int bh = blockIdx.x;
    int b = bh / Hc, h = bh % Hc;
    int t = threadIdx.x;
    int i = t >> 5, j = t & 31;
    const float* qb = g_qblk + ((size_t)bh * NBc + i) * Dc;
    const float* kb = g_kblk + ((size_t)(b * HKVc + (h >> 2)) * NBc + j) * Dc;
    float dot = 0.f;
#pragma unroll 8
    for (int d = 0; d < Dc; d++) dot = fmaf(qb[d], kb[d], dot);
    bool hard = (dot * SCALEc >= 0.0f) || (i == j);
    hard = hard && (j <= i);
    unsigned bits = __ballot_sync(0xffffffffu, hard);
    if (j == 0) g_mask[(size_t)bh * NBc + i] = bits;
}

// ---------------- block-sparse flash attention, fp16 tensor cores ----------------
// CTA = (ib, h, b), 128 threads (4 warps); warp w owns query rows 16w..16w+15.
// smem tiles Qh Ql Kh Kl Vh Vl: 64 rows x 128 halfs, row stride 272 B
// (272 B = 68 banks -> ldmatrix 8-row groups hit distinct bank quads).
#define FSTRIDE 272
#define FTILE_B (64 * FSTRIDE)             // 17408 B
#define FLASH_SMEM (6 * FTILE_B)           // 104448 B

__global__ void __launch_bounds__(128, 2) flash_h()
{
    extern __shared__ char smc[];
    const uint32_t sb = smem_u32(smc);
    const uint32_t Qh = sb,               Ql = sb + FTILE_B;
    const uint32_t Kh = sb + 2 * FTILE_B, Kl = sb + 3 * FTILE_B;
    const uint32_t Vh = sb + 4 * FTILE_B, Vl = sb + 5 * FTILE_B;

    const int ib = blockIdx.x, h = blockIdx.y, b = blockIdx.z;
    const int tid = threadIdx.x, wid = tid >> 5, lane = tid & 31;
    const int g = lane >> 2, q = lane & 3;
    const int lrow = lane & 15;
    const uint32_t lcol = (uint32_t)(lane >> 4) * 16;

    const size_t qoff = ((size_t)(b * Hc + h) * Sc + (size_t)ib * 64) * Dc;
    const size_t koff = ((size_t)(b * HKVc + (h >> 2)) * Sc) * Dc;
    const unsigned maskrow = g_mask[(size_t)(b * Hc + h) * NBc + ib];

    // load Q limbs
    for (int slot = tid; slot < 1024; slot += 128) {
        int r = slot >> 4, s = slot & 15;
        int so = r * FSTRIDE + s * 16, go = r * 128 + s * 8;
        *(uint4*)(smc + so)           = *(const uint4*)(g_qh + qoff + go);
        *(uint4*)(smc + FTILE_B + so) = *(const uint4*)(g_ql + qoff + go);
    }

    float acc[16][4];
#pragma unroll
    for (int nt = 0; nt < 16; nt++)
#pragma unroll
        for (int c = 0; c < 4; c++) acc[nt][c] = 0.f;
    float m0 = -1e38f, m1 = -1e38f, l0 = 0.f, l1 = 0.f;
    __syncthreads();

    for (int jb = 0; jb <= ib; jb++) {
        if (!((maskrow >> jb) & 1u)) continue;
        const bool diag = (jb == ib);
        const size_t kvo = koff + (size_t)jb * 64 * Dc;

        for (int slot = tid; slot < 1024; slot += 128) {
            int r = slot >> 4, s = slot & 15;
            int so = r * FSTRIDE + s * 16, go = r * 128 + s * 8;
            *(uint4*)(smc + 2 * FTILE_B + so) = *(const uint4*)(g_kh + kvo + go);
            *(uint4*)(smc + 3 * FTILE_B + so) = *(const uint4*)(g_kl + kvo + go);
            *(uint4*)(smc + 4 * FTILE_B + so) = *(const uint4*)(g_vh + kvo + go);
            *(uint4*)(smc + 5 * FTILE_B + so) = *(const uint4*)(g_vl + kvo + go);
        }
        __syncthreads();

        // ---- QK^T (2-limb, 3 products) ----
        float s8[8][4];
#pragma unroll
        for (int nt = 0; nt < 8; nt++)
#pragma unroll
            for (int c = 0; c < 4; c++) s8[nt][c] = 0.f;

#pragma unroll
        for (int kb = 0; kb < 8; kb++) {
            const uint32_t ko = kb * 32 + lcol;
            uint32_t ah[4], al[4], bh[8][2], bl[8][2], r4[4];
            ldm4(Qh + (16 * wid + lrow) * FSTRIDE + ko, ah);
            ldm4(Ql + (16 * wid + lrow) * FSTRIDE + ko, al);
#pragma unroll
            for (int p = 0; p < 4; p++) {
                ldm4(Kh + (p * 16 + lrow) * FSTRIDE + ko, r4);
                bh[2 * p][0] = r4[0]; bh[2 * p + 1][0] = r4[1];
                bh[2 * p][1] = r4[2]; bh[2 * p + 1][1] = r4[3];
                ldm4(Kl + (p * 16 + lrow) * FSTRIDE + ko, r4);
                bl[2 * p][0] = r4[0]; bl[2 * p + 1][0] = r4[1];
                bl[2 * p][1] = r4[2]; bl[2 * p + 1][1] = r4[3];
            }
#pragma unroll
            for (int nt = 0; nt < 8; nt++) {
                MMA_F16(s8[nt], ah, bh[nt]);
                MMA_F16(s8[nt], ah, bl[nt]);
                MMA_F16(s8[nt], al, bh[nt]);
            }
        }

        // ---- online softmax ----
        float mb0 = -1e38f, mb1 = -1e38f;
#pragma unroll
        for (int nt = 0; nt < 8; nt++)
#pragma unroll
            for (int c = 0; c < 4; c++) {
                float v = s8[nt][c] * SCALEc;
                if (diag) {
                    int col = nt * 8 + 2 * q + (c & 1);
                    int row = 16 * wid + g + (c >> 1) * 8;
                    if (col > row) v = -1e30f;
                }
                s8[nt][c] = v;
                if (c < 2) mb0 = fmaxf(mb0, v); else mb1 = fmaxf(mb1, v);
            }
        mb0 = fmaxf(mb0, __shfl_xor_sync(0xffffffffu, mb0, 1));
        mb0 = fmaxf(mb0, __shfl_xor_sync(0xffffffffu, mb0, 2));
        mb1 = fmaxf(mb1, __shfl_xor_sync(0xffffffffu, mb1, 1));
        mb1 = fmaxf(mb1, __shfl_xor_sync(0xffffffffu, mb1, 2));
        float mn0 = fmaxf(m0, mb0), mn1 = fmaxf(m1, mb1);
        float a0 = __expf(m0 - mn0), a1 = __expf(m1 - mn1);
        m0 = mn0; m1 = mn1;
        float ls0 = 0.f, ls1 = 0.f;
#pragma unroll
        for (int nt = 0; nt < 8; nt++) {
            float p0 = __expf(s8[nt][0] - mn0); s8[nt][0] = p0; ls0 += p0;
            float p1 = __expf(s8[nt][1] - mn0); s8[nt][1] = p1; ls0 += p1;
            float p2 = __expf(s8[nt][2] - mn1); s8[nt][2] = p2; ls1 += p2;
            float p3 = __expf(s8[nt][3] - mn1); s8[nt][3] = p3; ls1 += p3;
        }
        ls0 += __shfl_xor_sync(0xffffffffu, ls0, 1);
        ls0 += __shfl_xor_sync(0xffffffffu, ls0, 2);
        ls1 += __shfl_xor_sync(0xffffffffu, ls1, 1);
        ls1 += __shfl_xor_sync(0xffffffffu, ls1, 2);
        l0 = l0 * a0 + ls0;
        l1 = l1 * a1 + ls1;
#pragma unroll
        for (int nt = 0; nt < 16; nt++) {
            acc[nt][0] *= a0; acc[nt][1] *= a0;
            acc[nt][2] *= a1; acc[nt][3] *= a1;
        }

        // ---- P(fp16) @ V(2-limb): acc += P*Vh + P*Vl ----
        uint32_t pa[4][4];
#pragma unroll
        for (int kc = 0; kc < 4; kc++) {
            pa[kc][0] = packh2(s8[2 * kc][0],     s8[2 * kc][1]);
            pa[kc][1] = packh2(s8[2 * kc][2],     s8[2 * kc][3]);
            pa[kc][2] = packh2(s8[2 * kc + 1][0], s8[2 * kc + 1][1]);
            pa[kc][3] = packh2(s8[2 * kc + 1][2], s8[2 * kc + 1][3]);
        }
#pragma unroll
        for (int kc = 0; kc < 4; kc++) {
#pragma unroll
            for (int dp = 0; dp < 8; dp++) {
                uint32_t r4[4];
                ldm4t(Vh + (kc * 16 + lrow) * FSTRIDE + dp * 32 + lcol, r4);
                MMA_F16(acc[2 * dp],     pa[kc], r4);
                MMA_F16(acc[2 * dp + 1], pa[kc], r4 + 2);
                ldm4t(Vl + (kc * 16 + lrow) * FSTRIDE + dp * 32 + lcol, r4);
                MMA_F16(acc[2 * dp],     pa[kc], r4);
                MMA_F16(acc[2 * dp + 1], pa[kc], r4 + 2);
            }
        }
        __syncthreads();   // K/V reads done before next iter's stores
    }

    // ---- epilogue: normalize, split to fp16 limbs, write (B,S,H*D) ----
    float inv0 = 1.f / l0, inv1 = 1.f / l1;
    size_t row0 = (size_t)b * Sc + (size_t)ib * 64 + 16 * wid + g;
#pragma unroll
    for (int nt = 0; nt < 16; nt++) {
        size_t off0 = row0 * 2048 + h * 128 + nt * 8 + 2 * q;
        size_t off1 = (row0 + 8) * 2048 + h * 128 + nt * 8 + 2 * q;
        float x0 = acc[nt][0] * inv0, x1 = acc[nt][1] * inv0;
        float x2 = acc[nt][2] * inv1, x3 = acc[nt][3] * inv1;
        __half h0 = __float2half_rn(x0), h1 = __float2half_rn(x1);
        __half h2 = __float2half_rn(x2), h3 = __float2half_rn(x3);
        *(__half2*)(g_ath + off0) = __halves2half2(h0, h1);
        *(__half2*)(g_ath + off1) = __halves2half2(h2, h3);
        *(__half2*)(g_atl + off0) = __halves2half2(
            __float2half_rn(x0 - __half2float(h0)), __float2half_rn(x1 - __half2float(h1)));
        *(__half2*)(g_atl + off1) = __halves2half2(
            __float2half_rn(x2 - __half2float(h2)), __float2half_rn(x3 - __half2float(h3)));
    }
}

// ---------------- launch ----------------
extern "C" void kernel_launch(void* const* d_in, const int* in_sizes, int n_in,
                              void* d_out, int out_size)
{
    const float* hidden = (const float*)d_in[0];
    const float* cosb   = (const float*)d_in[1];
    const float* sinb   = (const float*)d_in[2];
    const float* Wq     = (const float*)d_in[3];
    const float* Wk     = (const float*)d_in[4];
    const float* Wv     = (const float*)d_in[5];
    const float* Wo     = (const float*)d_in[6];
    float* out = (float*)d_out;

    float *qkv, *qblk, *kblk;
    __half *hh, *hl, *wth, *wtl, *woth, *wotl, *ath, *atl, *qh, *ql, *kh, *kl;
    cudaGetSymbolAddress((void**)&qkv,  g_qkv);
    cudaGetSymbolAddress((void**)&qblk, g_qblk);
    cudaGetSymbolAddress((void**)&kblk, g_kblk);
    cudaGetSymbolAddress((void**)&hh,   g_hh);
    cudaGetSymbolAddress((void**)&hl,   g_hl);
    cudaGetSymbolAddress((void**)&wth,  g_wth);
    cudaGetSymbolAddress((void**)&wtl,  g_wtl);
    cudaGetSymbolAddress((void**)&woth, g_woth);
    cudaGetSymbolAddress((void**)&wotl, g_wotl);
    cudaGetSymbolAddress((void**)&ath,  g_ath);
    cudaGetSymbolAddress((void**)&atl,  g_atl);
    cudaGetSymbolAddress((void**)&qh,   g_qh);
    cudaGetSymbolAddress((void**)&ql,   g_ql);
    cudaGetSymbolAddress((void**)&kh,   g_kh);
    cudaGetSymbolAddress((void**)&kl,   g_kl);

    // 0. weights -> transposed fp16 limbs; hidden -> fp16 limbs
    transpose_split<<<dim3(64, 64), dim3(32, 8)>>>(Wq, wth, wtl, 2048, 2048);
    transpose_split<<<dim3(16, 64), dim3(32, 8)>>>(Wk, wth + (size_t)2048 * 2048,
                                                       wtl + (size_t)2048 * 2048, 2048, 512);
    transpose_split<<<dim3(16, 64), dim3(32, 8)>>>(Wv, wth + (size_t)2560 * 2048,
                                                       wtl + (size_t)2560 * 2048, 2048, 512);
    transpose_split<<<dim3(64, 64), dim3(32, 8)>>>(Wo, woth, wotl, 2048, 2048);
    split_kernel<<<8192, 256>>>(hidden, hh, hl, 4096 * 2048);

    cudaFuncSetAttribute(gemm_h, cudaFuncAttributeMaxDynamicSharedMemorySize, GEMM_SMEM);

    // 1. fused QKV projection
    gemm_h<<<dim3(24, 32), 256, GEMM_SMEM>>>(hh, hl, wth, wtl, qkv, 3072, 2048);

    // 2. RoPE -> fp16 limbs (q/k/v in head-major layout)
    rope_h<<<dim3(Sc, Bc), 256>>>(qkv, cosb, sinb);

    // 3. block means (from limbs)
    blockmean_h<<<dim3(NBc, Hc,   Bc), 128>>>(qh, ql, qblk, Hc);
    blockmean_h<<<dim3(NBc, HKVc, Bc), 128>>>(kh, kl, kblk, HKVc);

    // 4. gate bitmask
    mask_kernel<<<Bc * Hc, 1024>>>();

    // 5. block-sparse flash attention (fp16 tensor cores), writes attn limbs
    cudaFuncSetAttribute(flash_h, cudaFuncAttributeMaxDynamicSharedMemorySize, FLASH_SMEM);
    flash_h<<<dim3(NBc, Hc, Bc), 128, FLASH_SMEM>>>();

    // 6. output projection
    gemm_h<<<dim3(16, 32), 256, GEMM_SMEM>>>(ath, atl, woth, wotl, out, 2048, 2048);
}

// round 11
// speedup vs baseline: 1.8220x; 1.8220x over previous
#include <cuda_runtime.h>
#include <cuda_fp16.h>
#include <math.h>
#include <cstdint>

// Problem constants
#define Bc   2
#define Sc   2048
#define HIDc 2048
#define Hc   16
#define HKVc 4
#define Dc   128
#define BSc  64
#define NBc  32
#define SCALEc 0.08838834764831845f   // 1/sqrt(128)

// ---------------- scratch (device globals; no allocation allowed) ----------------
__device__ float    g_qkv[(size_t)4096 * 3072];          // hidden @ [Wq|Wk|Wv]
__device__ float    g_qblk[Bc * Hc   * NBc * Dc];
__device__ float    g_kblk[Bc * HKVc * NBc * Dc];
__device__ unsigned g_mask[Bc * Hc * NBc];               // bit j of row i: block (i,j) active

// fp16 limb arrays (value = hi + lo)
__device__ __half g_hh [(size_t)4096 * 2048];   // hidden hi
__device__ __half g_hl [(size_t)4096 * 2048];   // hidden lo
__device__ __half g_wth[(size_t)3072 * 2048];   // [Wq^T;Wk^T;Wv^T] hi  (rows=N, cols=K)
__device__ __half g_wtl[(size_t)3072 * 2048];
__device__ __half g_woth[(size_t)2048 * 2048];  // Wo^T hi
__device__ __half g_wotl[(size_t)2048 * 2048];
__device__ __half g_ath[(size_t)4096 * 2048];   // attn out hi (B,S,H*D)
__device__ __half g_atl[(size_t)4096 * 2048];
// roped q/k limbs (k lo used only by blockmean), v hi
__device__ __half g_qh[(size_t)Bc * Hc   * Sc * Dc];
__device__ __half g_ql[(size_t)Bc * Hc   * Sc * Dc];
__device__ __half g_kh[(size_t)Bc * HKVc * Sc * Dc];
__device__ __half g_kl[(size_t)Bc * HKVc * Sc * Dc];
__device__ __half g_vh[(size_t)Bc * HKVc * Sc * Dc];

// ======================= helpers =======================
__device__ __forceinline__ uint32_t smem_u32(const void* p) {
    uint32_t a;
    asm("{ .reg .u64 t; cvta.to.shared.u64 t, %1; cvt.u32.u64 %0, t; }" : "=r"(a) : "l"(p));
    return a;
}
__device__ __forceinline__ void ldm4(uint32_t addr, uint32_t* r) {
    asm volatile("ldmatrix.sync.aligned.m8n8.x4.shared.b16 {%0,%1,%2,%3}, [%4];"
        : "=r"(r[0]), "=r"(r[1]), "=r"(r[2]), "=r"(r[3]) : "r"(addr));
}
__device__ __forceinline__ void ldm4t(uint32_t addr, uint32_t* r) {
    asm volatile("ldmatrix.sync.aligned.m8n8.x4.trans.shared.b16 {%0,%1,%2,%3}, [%4];"
        : "=r"(r[0]), "=r"(r[1]), "=r"(r[2]), "=r"(r[3]) : "r"(addr));
}
#define MMA_F16(d, a, b) \
    asm volatile("mma.sync.aligned.m16n8k16.row.col.f32.f16.f16.f32 " \
        "{%0,%1,%2,%3}, {%4,%5,%6,%7}, {%8,%9}, {%0,%1,%2,%3};" \
        : "+f"((d)[0]), "+f"((d)[1]), "+f"((d)[2]), "+f"((d)[3]) \
        : "r"((a)[0]), "r"((a)[1]), "r"((a)[2]), "r"((a)[3]), \
          "r"((b)[0]), "r"((b)[1]))
#define CP_ASYNC16(dst, src) \
    asm volatile("cp.async.cg.shared.global [%0], [%1], 16;" :: "r"(dst), "l"(src))
#define CP_COMMIT()  asm volatile("cp.async.commit_group;" ::: "memory")
#define CP_WAIT1()   asm volatile("cp.async.wait_group 1;" ::: "memory")
#define CP_WAIT0()   asm volatile("cp.async.wait_group 0;" ::: "memory")

__device__ __forceinline__ void wsplit(__half* ph, __half* pl, size_t i, float v) {
    __half h = __float2half_rn(v);
    ph[i] = h;
    pl[i] = __float2half_rn(v - __half2float(h));
}
__device__ __forceinline__ uint32_t packh2(float x, float y) {
    __half2 h = __floats2half2_rn(x, y);
    return *(uint32_t*)&h;
}

// ================== fp16 split GEMM: C[M,*] = (A) @ (Bt)^T ==================
// NPROD=3: ah*bh + ah*bl + al*bh (fp32-grade). NPROD=2: ah*bh + al*bh (~2.4e-4).
#define KCH     32
#define TROW    40                         // halfs per smem row
#define TILE_B  (128 * TROW * 2)           // 10240 B
#define STAGE_B (4 * TILE_B)               // 40960 B
#define GEMM_SMEM (2 * STAGE_B)            // 81920 B

template <int NPROD>
__global__ void __launch_bounds__(256, 2) gemm_h(
    const __half* __restrict__ Ahg, const __half* __restrict__ Alg,
    const __half* __restrict__ Bhg, const __half* __restrict__ Blg,
    float* __restrict__ C, int ldc, int K)
{
    extern __shared__ char smc[];
    const uint32_t sb = smem_u32(smc);
    const int tid = threadIdx.x;
    const int wid = tid >> 5, lane = tid & 31;
    const int wm = wid & 1, wn = wid >> 1;
    const int g = lane >> 2, q = lane & 3;
    const int row0 = blockIdx.y * 128;
    const int col0 = blockIdx.x * 128;
    const __half* A0 = Ahg + (size_t)row0 * K;
    const __half* A1 = Alg + (size_t)row0 * K;
    const __half* B0 = Bhg + (size_t)col0 * K;
    const __half* B1 = Blg + (size_t)col0 * K;

    float acc[4][4][4];
#pragma unroll
    for (int t = 0; t < 4; t++)
#pragma unroll
        for (int u = 0; u < 4; u++)
#pragma unroll
            for (int r = 0; r < 4; r++) acc[t][u][r] = 0.f;

    const int lrow = lane & 15;
    const uint32_t lk = (uint32_t)(lane >> 4) * 16;

    auto prefetch = [&](int kc, int s) {
        const int k0 = kc * KCH;
        const uint32_t st = sb + s * STAGE_B;
        const __half* gs[4] = {A0, A1, B0, B1};
        const int nop = (NPROD == 3) ? 4 : 3;
        for (int t4 = 0; t4 < nop; t4++) {
#pragma unroll
            for (int j = 0; j < 2; j++) {
                int idx = tid + j * 256;
                int row = idx >> 2, seg = idx & 3;
                uint32_t dst = st + t4 * TILE_B + row * 80 + seg * 16;
                const __half* src = gs[t4] + (size_t)row * K + k0 + seg * 8;
                CP_ASYNC16(dst, src);
            }
        }
    };

    auto compute = [&](int s) {
        const uint32_t st = sb + s * STAGE_B;
#pragma unroll
        for (int kb = 0; kb < 2; kb++) {
            const uint32_t ko = kb * 32 + lk;
            uint32_t a[4][4], b[4][2], r[4];
#pragma unroll
            for (int p = 0; p < 2; p++) {
                ldm4(st + 2 * TILE_B + (wn * 32 + p * 16 + lrow) * 80 + ko, r);
                b[2 * p][0] = r[0]; b[2 * p + 1][0] = r[1];
                b[2 * p][1] = r[2]; b[2 * p + 1][1] = r[3];
            }
#pragma unroll
            for (int t = 0; t < 4; t++)
                ldm4(st + (wm * 64 + t * 16 + lrow) * 80 + ko, a[t]);
#pragma unroll
            for (int t = 0; t < 4; t++)
#pragma unroll
                for (int u = 0; u < 4; u++) MMA_F16(acc[t][u], a[t], b[u]);
            if (NPROD == 3) {
                uint32_t b2[4][2];
#pragma unroll
                for (int p = 0; p < 2; p++) {
                    ldm4(st + 3 * TILE_B + (wn * 32 + p * 16 + lrow) * 80 + ko, r);
                    b2[2 * p][0] = r[0]; b2[2 * p + 1][0] = r[1];
                    b2[2 * p][1] = r[2]; b2[2 * p + 1][1] = r[3];
                }
#pragma unroll
                for (int t = 0; t < 4; t++)
#pragma unroll
                    for (int u = 0; u < 4; u++) MMA_F16(acc[t][u], a[t], b2[u]);
            }
#pragma unroll
            for (int t = 0; t < 4; t++)
                ldm4(st + TILE_B + (wm * 64 + t * 16 + lrow) * 80 + ko, a[t]);
#pragma unroll
            for (int t = 0; t < 4; t++)
#pragma unroll
                for (int u = 0; u < 4; u++) MMA_F16(acc[t][u], a[t], b[u]);
        }
    };

    const int nch = K / KCH;
    prefetch(0, 0); CP_COMMIT();
    prefetch(1, 1); CP_COMMIT();
    for (int kc = 0; kc < nch; kc++) {
        int s = kc & 1;
        if (kc + 1 < nch) { CP_WAIT1(); } else { CP_WAIT0(); }
        __syncthreads();
        compute(s);
        __syncthreads();
        if (kc + 2 < nch) prefetch(kc + 2, s);
        CP_COMMIT();
    }

#pragma unroll
    for (int t = 0; t < 4; t++) {
        int r = row0 + wm * 64 + t * 16 + g;
#pragma unroll
        for (int u = 0; u < 4; u++) {
            int c = col0 + wn * 32 + u * 8 + q * 2;
            *(float2*)(C + (size_t)r * ldc + c)       = make_float2(acc[t][u][0], acc[t][u][1]);
            *(float2*)(C + (size_t)(r + 8) * ldc + c) = make_float2(acc[t][u][2], acc[t][u][3]);
        }
    }
}

// ---------------- transpose + fp16 limb split ----------------
__global__ __launch_bounds__(256) void transpose_split(
    const float* __restrict__ in, __half* __restrict__ oh, __half* __restrict__ ol,
    int Kdim, int Ndim)
{
    __shared__ float t[32][33];
    int bx = blockIdx.x * 32, by = blockIdx.y * 32;
    int x = threadIdx.x, y = threadIdx.y;
#pragma unroll
    for (int i = 0; i < 32; i += 8)
        t[y + i][x] = in[(size_t)(by + y + i) * Ndim + bx + x];
    __syncthreads();
#pragma unroll
    for (int i = 0; i < 32; i += 8)
        wsplit(oh, ol, (size_t)(bx + y + i) * Kdim + by + x, t[x][y + i]);
}

// ---------------- fp16 limb split (no transpose) ----------------
__global__ __launch_bounds__(256) void split_kernel(
    const float* __restrict__ in, __half* __restrict__ oh, __half* __restrict__ ol, int n)
{
    int i = (blockIdx.x * 256 + threadIdx.x) * 4;
    if (i >= n) return;
    float4 v = *(const float4*)(in + i);
    wsplit(oh, ol, i,     v.x);
    wsplit(oh, ol, i + 1, v.y);
    wsplit(oh, ol, i + 2, v.z);
    wsplit(oh, ol, i + 3, v.w);
}

// ---------------- RoPE + reshape -> fp16 limbs ----------------
__global__ void rope_h(const float* __restrict__ qkv,
                       const float* __restrict__ cosb,
                       const float* __restrict__ sinb)
{
    int s = blockIdx.x, b = blockIdx.y;
    const float* row = qkv + (size_t)(b * Sc + s) * 3072;
    const float* cr  = cosb + (size_t)(b * Sc + s) * Dc;
    const float* sr  = sinb + (size_t)(b * Sc + s) * Dc;
    int t = threadIdx.x;

    for (int p = t; p < Hc * 64; p += 256) {            // q pairs
        int h = p >> 6, d = p & 63;
        float x1 = row[h * 128 + d], x2 = row[h * 128 + d + 64];
        size_t base = ((size_t)(b * Hc + h) * Sc + s) * Dc;
        wsplit(g_qh, g_ql, base + d,      x1 * cr[d]      - x2 * sr[d]);
        wsplit(g_qh, g_ql, base + d + 64, x2 * cr[d + 64] + x1 * sr[d + 64]);
    }
    for (int p = t; p < HKVc * 64; p += 256) {          // k pairs
        int h = p >> 6, d = p & 63;
        float x1 = row[2048 + h * 128 + d], x2 = row[2048 + h * 128 + d + 64];
        size_t base = ((size_t)(b * HKVc + h) * Sc + s) * Dc;
        wsplit(g_kh, g_kl, base + d,      x1 * cr[d]      - x2 * sr[d]);
        wsplit(g_kh, g_kl, base + d + 64, x2 * cr[d + 64] + x1 * sr[d + 64]);
    }
    for (int p = t; p < HKVc * Dc; p += 256) {          // v (hi only)
        int h = p >> 7, d = p & 127;
        size_t base = ((size_t)(b * HKVc + h) * Sc + s) * Dc;
        g_vh[base + d] = __float2half_rn(row[2560 + h * 128 + d]);
    }
}

// ---------------- block means over BS=64 rows (from limbs; fp32-grade) ----------------
__global__ void blockmean_h(const __half* __restrict__ xh, const __half* __restrict__ xl,
                            float* __restrict__ out, int HH)
{
    int i = blockIdx.x, h = blockIdx.y, b = blockIdx.z, d = threadIdx.x;
    size_t base = ((size_t)(b * HH + h) * Sc + i * BSc) * Dc + d;
    float sum = 0.f;
#pragma unroll
    for (int r = 0; r < BSc; r++) {
        size_t idx = base + (size_t)r * Dc;
        sum += __half2float(xh[idx]) + __half2float(xl[idx]);
    }
    out[((size_t)(b * HH + h) * NBc + i) * Dc + d] = sum * (1.0f / 64.0f);
}

// ---------------- gate mask ----------------
__global__ __launch_bounds__(1024) void mask_kernel()
{
    int bh = blockIdx.x;
    int b = bh / Hc, h = bh % Hc;
    int t = threadIdx.x;
    int i = t >> 5, j = t & 31;
    const float* qb = g_qblk + ((size_t)bh * NBc + i) * Dc;
    const float* kb = g_kblk + ((size_t)(b * HKVc + (h >> 2)) * NBc + j) * Dc;
    float dot = 0.f;
#pragma unroll 8
    for (int d = 0; d < Dc; d++) dot = fmaf(qb[d], kb[d], dot);
    bool hard = (dot * SCALEc >= 0.0f) || (i == j);
    hard = hard && (j <= i);
    unsigned bits = __ballot_sync(0xffffffffu, hard);
    if (j == 0) g_mask[(size_t)bh * NBc + i] = bits;
}

// ---------------- block-sparse flash attention, fp16 tensor cores ----------------
// CTA = (ib, h, b), 128 threads; warp w owns query rows 16w..16w+15.
// smem tiles Qh Ql Kh Vh: 64 rows x 128 halfs, row stride 272 B.
// QK = QhKh + QlKh (2 products); PV = P*Vh (1 product).
#define FSTRIDE 272
#define FTILE_B (64 * FSTRIDE)             // 17408 B
#define FLASH_SMEM (4 * FTILE_B)           // 69632 B

__global__ void __launch_bounds__(128, 3) flash_h()
{
    extern __shared__ char smc[];
    const uint32_t sb = smem_u32(smc);
    const uint32_t Qh = sb,               Ql = sb + FTILE_B;
    const uint32_t Kh = sb + 2 * FTILE_B, Vh = sb + 3 * FTILE_B;

    const int ib = blockIdx.x, h = blockIdx.y, b = blockIdx.z;
    const int tid = threadIdx.x, wid = tid >> 5, lane = tid & 31;
    const int g = lane >> 2, q = lane & 3;
    const int lrow = lane & 15;
    const uint32_t lcol = (uint32_t)(lane >> 4) * 16;

    const size_t qoff = ((size_t)(b * Hc + h) * Sc + (size_t)ib * 64) * Dc;
    const size_t koff = ((size_t)(b * HKVc + (h >> 2)) * Sc) * Dc;
    const unsigned maskrow = g_mask[(size_t)(b * Hc + h) * NBc + ib];

    // load Q limbs
    for (int slot = tid; slot < 1024; slot += 128) {
        int r = slot >> 4, s = slot & 15;
        int so = r * FSTRIDE + s * 16, go = r * 128 + s * 8;
        *(uint4*)(smc + so)           = *(const uint4*)(g_qh + qoff + go);
        *(uint4*)(smc + FTILE_B + so) = *(const uint4*)(g_ql + qoff + go);
    }

    float acc[16][4];
#pragma unroll
    for (int nt = 0; nt < 16; nt++)
#pragma unroll
        for (int c = 0; c < 4; c++) acc[nt][c] = 0.f;
    float m0 = -1e38f, m1 = -1e38f, l0 = 0.f, l1 = 0.f;
    __syncthreads();

    for (int jb = 0; jb <= ib; jb++) {
        if (!((maskrow >> jb) & 1u)) continue;
        const bool diag = (jb == ib);
        const size_t kvo = koff + (size_t)jb * 64 * Dc;

        for (int slot = tid; slot < 1024; slot += 128) {
            int r = slot >> 4, s = slot & 15;
            int so = r * FSTRIDE + s * 16, go = r * 128 + s * 8;
            *(uint4*)(smc + 2 * FTILE_B + so) = *(const uint4*)(g_kh + kvo + go);
            *(uint4*)(smc + 3 * FTILE_B + so) = *(const uint4*)(g_vh + kvo + go);
        }
        __syncthreads();

        // ---- QK^T (Q 2-limb x K hi) ----
        float s8[8][4];
#pragma unroll
        for (int nt = 0; nt < 8; nt++)
#pragma unroll
            for (int c = 0; c < 4; c++) s8[nt][c] = 0.f;

#pragma unroll
        for (int kb = 0; kb < 8; kb++) {
            const uint32_t ko = kb * 32 + lcol;
            uint32_t ah[4], al[4], bh[8][2], r4[4];
            ldm4(Qh + (16 * wid + lrow) * FSTRIDE + ko, ah);
            ldm4(Ql + (16 * wid + lrow) * FSTRIDE + ko, al);
#pragma unroll
            for (int p = 0; p < 4; p++) {
                ldm4(Kh + (p * 16 + lrow) * FSTRIDE + ko, r4);
                bh[2 * p][0] = r4[0]; bh[2 * p + 1][0] = r4[1];
                bh[2 * p][1] = r4[2]; bh[2 * p + 1][1] = r4[3];
            }
#pragma unroll
            for (int nt = 0; nt < 8; nt++) {
                MMA_F16(s8[nt], ah, bh[nt]);
                MMA_F16(s8[nt], al, bh[nt]);
            }
        }

        // ---- online softmax ----
        float mb0 = -1e38f, mb1 = -1e38f;
#pragma unroll
        for (int nt = 0; nt < 8; nt++)
#pragma unroll
            for (int c = 0; c < 4; c++) {
                float v = s8[nt][c] * SCALEc;
                if (diag) {
                    int col = nt * 8 + 2 * q + (c & 1);
                    int row = 16 * wid + g + (c >> 1) * 8;
                    if (col > row) v = -1e30f;
                }
                s8[nt][c] = v;
                if (c < 2) mb0 = fmaxf(mb0, v); else mb1 = fmaxf(mb1, v);
            }
        mb0 = fmaxf(mb0, __shfl_xor_sync(0xffffffffu, mb0, 1));
        mb0 = fmaxf(mb0, __shfl_xor_sync(0xffffffffu, mb0, 2));
        mb1 = fmaxf(mb1, __shfl_xor_sync(0xffffffffu, mb1, 1));
        mb1 = fmaxf(mb1, __shfl_xor_sync(0xffffffffu, mb1, 2));
        float mn0 = fmaxf(m0, mb0), mn1 = fmaxf(m1, mb1);
        float a0 = __expf(m0 - mn0), a1 = __expf(m1 - mn1);
        m0 = mn0; m1 = mn1;
        float ls0 = 0.f, ls1 = 0.f;
#pragma unroll
        for (int nt = 0; nt < 8; nt++) {
            float p0 = __expf(s8[nt][0] - mn0); s8[nt][0] = p0; ls0 += p0;
            float p1 = __expf(s8[nt][1] - mn0); s8[nt][1] = p1; ls0 += p1;
            float p2 = __expf(s8[nt][2] - mn1); s8[nt][2] = p2; ls1 += p2;
            float p3 = __expf(s8[nt][3] - mn1); s8[nt][3] = p3; ls1 += p3;
        }
        ls0 += __shfl_xor_sync(0xffffffffu, ls0, 1);
        ls0 += __shfl_xor_sync(0xffffffffu, ls0, 2);
        ls1 += __shfl_xor_sync(0xffffffffu, ls1, 1);
        ls1 += __shfl_xor_sync(0xffffffffu, ls1, 2);
        l0 = l0 * a0 + ls0;
        l1 = l1 * a1 + ls1;
#pragma unroll
        for (int nt = 0; nt < 16; nt++) {
            acc[nt][0] *= a0; acc[nt][1] *= a0;
            acc[nt][2] *= a1; acc[nt][3] *= a1;
        }

        // ---- P(fp16) @ V(hi) ----
        uint32_t pa[4][4];
#pragma unroll
        for (int kc = 0; kc < 4; kc++) {
            pa[kc][0] = packh2(s8[2 * kc][0],     s8[2 * kc][1]);
            pa[kc][1] = packh2(s8[2 * kc][2],     s8[2 * kc][3]);
            pa[kc][2] = packh2(s8[2 * kc + 1][0], s8[2 * kc + 1][1]);
            pa[kc][3] = packh2(s8[2 * kc + 1][2], s8[2 * kc + 1][3]);
        }
#pragma unroll
        for (int kc = 0; kc < 4; kc++) {
#pragma unroll
            for (int dp = 0; dp < 8; dp++) {
                uint32_t r4[4];
                ldm4t(Vh + (kc * 16 + lrow) * FSTRIDE + dp * 32 + lcol, r4);
                MMA_F16(acc[2 * dp],     pa[kc], r4);
                MMA_F16(acc[2 * dp + 1], pa[kc], r4 + 2);
            }
        }
        __syncthreads();   // K/V reads done before next iter's stores
    }

    // ---- epilogue: normalize, split to fp16 limbs, write (B,S,H*D) ----
    float inv0 = 1.f / l0, inv1 = 1.f / l1;
    size_t row0 = (size_t)b * Sc + (size_t)ib * 64 + 16 * wid + g;
#pragma unroll
    for (int nt = 0; nt < 16; nt++) {
        size_t off0 = row0 * 2048 + h * 128 + nt * 8 + 2 * q;
        size_t off1 = (row0 + 8) * 2048 + h * 128 + nt * 8 + 2 * q;
        float x0 = acc[nt][0] * inv0, x1 = acc[nt][1] * inv0;
        float x2 = acc[nt][2] * inv1, x3 = acc[nt][3] * inv1;
        __half h0 = __float2half_rn(x0), h1 = __float2half_rn(x1);
        __half h2 = __float2half_rn(x2), h3 = __float2half_rn(x3);
        *(__half2*)(g_ath + off0) = __halves2half2(h0, h1);
        *(__half2*)(g_ath + off1) = __halves2half2(h2, h3);
        *(__half2*)(g_atl + off0) = __halves2half2(
            __float2half_rn(x0 - __half2float(h0)), __float2half_rn(x1 - __half2float(h1)));
        *(__half2*)(g_atl + off1) = __halves2half2(
            __float2half_rn(x2 - __half2float(h2)), __float2half_rn(x3 - __half2float(h3)));
    }
}

// ---------------- launch ----------------
extern "C" void kernel_launch(void* const* d_in, const int* in_sizes, int n_in,
                              void* d_out, int out_size)
{
    const float* hidden = (const float*)d_in[0];
    const float* cosb   = (const float*)d_in[1];
    const float* sinb   = (const float*)d_in[2];
    const float* Wq     = (const float*)d_in[3];
    const float* Wk     = (const float*)d_in[4];
    const float* Wv     = (const float*)d_in[5];
    const float* Wo     = (const float*)d_in[6];
    float* out = (float*)d_out;

    float *qkv, *qblk, *kblk;
    __half *hh, *hl, *wth, *wtl, *woth, *wotl, *ath, *atl, *qh, *ql, *kh, *kl;
    cudaGetSymbolAddress((void**)&qkv,  g_qkv);
    cudaGetSymbolAddress((void**)&qblk, g_qblk);
    cudaGetSymbolAddress((void**)&kblk, g_kblk);
    cudaGetSymbolAddress((void**)&hh,   g_hh);
    cudaGetSymbolAddress((void**)&hl,   g_hl);
    cudaGetSymbolAddress((void**)&wth,  g_wth);
    cudaGetSymbolAddress((void**)&wtl,  g_wtl);
    cudaGetSymbolAddress((void**)&woth, g_woth);
    cudaGetSymbolAddress((void**)&wotl, g_wotl);
    cudaGetSymbolAddress((void**)&ath,  g_ath);
    cudaGetSymbolAddress((void**)&atl,  g_atl);
    cudaGetSymbolAddress((void**)&qh,   g_qh);
    cudaGetSymbolAddress((void**)&ql,   g_ql);
    cudaGetSymbolAddress((void**)&kh,   g_kh);
    cudaGetSymbolAddress((void**)&kl,   g_kl);

    // 0. weights -> transposed fp16 limbs; hidden -> fp16 limbs
    transpose_split<<<dim3(64, 64), dim3(32, 8)>>>(Wq, wth, wtl, 2048, 2048);
    transpose_split<<<dim3(16, 64), dim3(32, 8)>>>(Wk, wth + (size_t)2048 * 2048,
                                                       wtl + (size_t)2048 * 2048, 2048, 512);
    transpose_split<<<dim3(16, 64), dim3(32, 8)>>>(Wv, wth + (size_t)2560 * 2048,
                                                       wtl + (size_t)2560 * 2048, 2048, 512);
    transpose_split<<<dim3(64, 64), dim3(32, 8)>>>(Wo, woth, wotl, 2048, 2048);
    split_kernel<<<8192, 256>>>(hidden, hh, hl, 4096 * 2048);

    cudaFuncSetAttribute(gemm_h<3>, cudaFuncAttributeMaxDynamicSharedMemorySize, GEMM_SMEM);
    cudaFuncSetAttribute(gemm_h<2>, cudaFuncAttributeMaxDynamicSharedMemorySize, GEMM_SMEM);

    // 1. QKV projection: q,k columns (mask-critical) 3-product; v columns 2-product
    gemm_h<3><<<dim3(20, 32), 256, GEMM_SMEM>>>(hh, hl, wth, wtl, qkv, 3072, 2048);
    gemm_h<2><<<dim3(4, 32), 256, GEMM_SMEM>>>(hh, hl,
        wth + (size_t)2560 * 2048, wtl + (size_t)2560 * 2048, qkv + 2560, 3072, 2048);

    // 2. RoPE -> fp16 limbs
    rope_h<<<dim3(Sc, Bc), 256>>>(qkv, cosb, sinb);

    // 3. block means (hi+lo; fp32-grade for the sign-critical mask)
    blockmean_h<<<dim3(NBc, Hc,   Bc), 128>>>(qh, ql, qblk, Hc);
    blockmean_h<<<dim3(NBc, HKVc, Bc), 128>>>(kh, kl, kblk, HKVc);

    // 4. gate bitmask
    mask_kernel<<<Bc * Hc, 1024>>>();

    // 5. block-sparse flash attention (fp16 tensor cores, trimmed limbs)
    cudaFuncSetAttribute(flash_h, cudaFuncAttributeMaxDynamicSharedMemorySize, FLASH_SMEM);
    flash_h<<<dim3(NBc, Hc, Bc), 128, FLASH_SMEM>>>();

    // 6. output projection (2-product suffices for 1e-3 output budget)
    gemm_h<2><<<dim3(16, 32), 256, GEMM_SMEM>>>(ath, atl, woth, wotl, out, 2048, 2048);
}

// round 17
// speedup vs baseline: 1.9544x; 1.0727x over previous
#include <cuda_runtime.h>
#include <cuda_fp16.h>
#include <math.h>
#include <cstdint>

// Problem constants
#define Bc   2
#define Sc   2048
#define HIDc 2048
#define Hc   16
#define HKVc 4
#define Dc   128
#define BSc  64
#define NBc  32
#define SCALEc 0.08838834764831845f   // 1/sqrt(128)

// ---------------- scratch (device globals; no allocation allowed) ----------------
__device__ float    g_qkv[(size_t)4096 * 3072];          // hidden @ [Wq|Wk|Wv]
__device__ float    g_qblk[Bc * Hc   * NBc * Dc];
__device__ float    g_kblk[Bc * HKVc * NBc * Dc];
__device__ unsigned g_mask[Bc * Hc * NBc];               // bit j of row i: block (i,j) active

// fp16 limb arrays (value = hi + lo)
__device__ __half g_hh [(size_t)4096 * 2048];   // hidden hi
__device__ __half g_hl [(size_t)4096 * 2048];   // hidden lo
__device__ __half g_wth[(size_t)3072 * 2048];   // [Wq^T;Wk^T;Wv^T] hi  (rows=N, cols=K)
__device__ __half g_wtl[(size_t)3072 * 2048];
__device__ __half g_woth[(size_t)2048 * 2048];  // Wo^T hi
__device__ __half g_wotl[(size_t)2048 * 2048];  // (unused by 1-prod Wo, kept for simplicity)
__device__ __half g_ath[(size_t)4096 * 2048];   // attn out hi (B,S,H*D)
// roped q/k limbs (k lo used only by blockmean), v hi
__device__ __half g_qh[(size_t)Bc * Hc   * Sc * Dc];
__device__ __half g_ql[(size_t)Bc * Hc   * Sc * Dc];
__device__ __half g_kh[(size_t)Bc * HKVc * Sc * Dc];
__device__ __half g_kl[(size_t)Bc * HKVc * Sc * Dc];
__device__ __half g_vh[(size_t)Bc * HKVc * Sc * Dc];

// ======================= helpers =======================
__device__ __forceinline__ uint32_t smem_u32(const void* p) {
    uint32_t a;
    asm("{ .reg .u64 t; cvta.to.shared.u64 t, %1; cvt.u32.u64 %0, t; }" : "=r"(a) : "l"(p));
    return a;
}
__device__ __forceinline__ void ldm4(uint32_t addr, uint32_t* r) {
    asm volatile("ldmatrix.sync.aligned.m8n8.x4.shared.b16 {%0,%1,%2,%3}, [%4];"
        : "=r"(r[0]), "=r"(r[1]), "=r"(r[2]), "=r"(r[3]) : "r"(addr));
}
__device__ __forceinline__ void ldm4t(uint32_t addr, uint32_t* r) {
    asm volatile("ldmatrix.sync.aligned.m8n8.x4.trans.shared.b16 {%0,%1,%2,%3}, [%4];"
        : "=r"(r[0]), "=r"(r[1]), "=r"(r[2]), "=r"(r[3]) : "r"(addr));
}
#define MMA_F16(d, a, b) \
    asm volatile("mma.sync.aligned.m16n8k16.row.col.f32.f16.f16.f32 " \
        "{%0,%1,%2,%3}, {%4,%5,%6,%7}, {%8,%9}, {%0,%1,%2,%3};" \
        : "+f"((d)[0]), "+f"((d)[1]), "+f"((d)[2]), "+f"((d)[3]) \
        : "r"((a)[0]), "r"((a)[1]), "r"((a)[2]), "r"((a)[3]), \
          "r"((b)[0]), "r"((b)[1]))
#define CP_ASYNC16(dst, src) \
    asm volatile("cp.async.cg.shared.global [%0], [%1], 16;" :: "r"(dst), "l"(src))
#define CP_COMMIT()  asm volatile("cp.async.commit_group;" ::: "memory")
#define CP_WAIT1()   asm volatile("cp.async.wait_group 1;" ::: "memory")
#define CP_WAIT0()   asm volatile("cp.async.wait_group 0;" ::: "memory")

__device__ __forceinline__ void wsplit(__half* ph, __half* pl, size_t i, float v) {
    __half h = __float2half_rn(v);
    ph[i] = h;
    pl[i] = __float2half_rn(v - __half2float(h));
}
__device__ __forceinline__ uint32_t packh2(float x, float y) {
    __half2 h = __floats2half2_rn(x, y);
    return *(uint32_t*)&h;
}

// ================== fp16 split GEMM: C[M,*] = (A) @ (Bt)^T ==================
// NPROD=3: ah*bh + ah*bl + al*bh (fp32-grade). NPROD=2: ah*bh + al*bh (~2.4e-4).
// NPROD=1: ah*bh (~4.9e-4). 3-stage cp.async pipeline, ONE __syncthreads per chunk.
// K-chunk 16; tiles stored as 128 contiguous 32B rows (4096 B/tile) ->
// each ldmatrix.x4 reads a contiguous 512B window: conflict-free.
#define KCH      16
#define GTILE_B  4096

template <int NPROD>
__global__ void __launch_bounds__(256, 2) gemm_h(
    const __half* __restrict__ Ahg, const __half* __restrict__ Alg,
    const __half* __restrict__ Bhg, const __half* __restrict__ Blg,
    float* __restrict__ C, int ldc, int K)
{
    constexpr int NOP    = (NPROD == 1) ? 2 : ((NPROD == 2) ? 3 : 4);
    constexpr int STAGEB = NOP * GTILE_B;
    constexpr uint32_t OFF_A1 = GTILE_B;
    constexpr uint32_t OFF_B0 = (NPROD == 1 ? 1 : 2) * GTILE_B;
    constexpr uint32_t OFF_B1 = 3 * GTILE_B;

    extern __shared__ char smc[];
    const uint32_t sb = smem_u32(smc);
    const int tid = threadIdx.x;
    const int wid = tid >> 5, lane = tid & 31;
    const int wm = wid & 1, wn = wid >> 1;     // warp grid 2(m) x 4(n), tile 64x32
    const int g = lane >> 2, q = lane & 3;
    const int row0 = blockIdx.y * 128;
    const int col0 = blockIdx.x * 128;
    const __half* A0 = Ahg + (size_t)row0 * K;
    const __half* A1 = Alg + (size_t)row0 * K;
    const __half* B0 = Bhg + (size_t)col0 * K;
    const __half* B1 = Blg + (size_t)col0 * K;

    const __half* gs[4];
    if (NPROD == 1)      { gs[0] = A0; gs[1] = B0; }
    else if (NPROD == 2) { gs[0] = A0; gs[1] = A1; gs[2] = B0; }
    else                 { gs[0] = A0; gs[1] = A1; gs[2] = B0; gs[3] = B1; }

    float acc[4][4][4];
#pragma unroll
    for (int t = 0; t < 4; t++)
#pragma unroll
        for (int u = 0; u < 4; u++)
#pragma unroll
            for (int r = 0; r < 4; r++) acc[t][u][r] = 0.f;

    const int lrow = lane & 15;
    const uint32_t lk = (uint32_t)(lane >> 4) * 16;   // 16B column half

    auto prefetch = [&](int kc, int s) {
        const int k0 = kc * KCH;
        const uint32_t st = sb + s * STAGEB;
        const int row = tid >> 1, seg = tid & 1;      // 256 chunks of 16B per tile
#pragma unroll
        for (int t4 = 0; t4 < NOP; t4++) {
            uint32_t dst = st + t4 * GTILE_B + row * 32 + seg * 16;
            const __half* src = gs[t4] + (size_t)row * K + k0 + seg * 8;
            CP_ASYNC16(dst, src);
        }
    };

    auto compute = [&](int s) {
        const uint32_t st = sb + s * STAGEB;
        uint32_t a[4][4], b[4][2], r[4];
        // B hi frags
#pragma unroll
        for (int p = 0; p < 2; p++) {
            ldm4(st + OFF_B0 + (wn * 32 + p * 16 + lrow) * 32 + lk, r);
            b[2 * p][0] = r[0]; b[2 * p + 1][0] = r[1];
            b[2 * p][1] = r[2]; b[2 * p + 1][1] = r[3];
        }
        // A hi frags
#pragma unroll
        for (int t = 0; t < 4; t++)
            ldm4(st + (wm * 64 + t * 16 + lrow) * 32 + lk, a[t]);
#pragma unroll
        for (int t = 0; t < 4; t++)
#pragma unroll
            for (int u = 0; u < 4; u++) MMA_F16(acc[t][u], a[t], b[u]);
        if (NPROD >= 3) {
            uint32_t b2[4][2];
#pragma unroll
            for (int p = 0; p < 2; p++) {
                ldm4(st + OFF_B1 + (wn * 32 + p * 16 + lrow) * 32 + lk, r);
                b2[2 * p][0] = r[0]; b2[2 * p + 1][0] = r[1];
                b2[2 * p][1] = r[2]; b2[2 * p + 1][1] = r[3];
            }
#pragma unroll
            for (int t = 0; t < 4; t++)
#pragma unroll
                for (int u = 0; u < 4; u++) MMA_F16(acc[t][u], a[t], b2[u]);
        }
        if (NPROD >= 2) {
            // A lo frags (overwrite hi)
#pragma unroll
            for (int t = 0; t < 4; t++)
                ldm4(st + OFF_A1 + (wm * 64 + t * 16 + lrow) * 32 + lk, a[t]);
#pragma unroll
            for (int t = 0; t < 4; t++)
#pragma unroll
                for (int u = 0; u < 4; u++) MMA_F16(acc[t][u], a[t], b[u]);
        }
    };

    const int nch = K / KCH;    // 128
    prefetch(0, 0); CP_COMMIT();
    prefetch(1, 1); CP_COMMIT();
    for (int kc = 0; kc < nch; kc++) {
        int s = kc % 3;
        if (kc + 1 < nch) { CP_WAIT1(); } else { CP_WAIT0(); }
        __syncthreads();
        compute(s);
        if (kc + 2 < nch) { prefetch(kc + 2, (kc + 2) % 3); CP_COMMIT(); }
    }

    // epilogue: regs -> C (f32)
#pragma unroll
    for (int t = 0; t < 4; t++) {
        int r = row0 + wm * 64 + t * 16 + g;
#pragma unroll
        for (int u = 0; u < 4; u++) {
            int c = col0 + wn * 32 + u * 8 + q * 2;
            *(float2*)(C + (size_t)r * ldc + c)       = make_float2(acc[t][u][0], acc[t][u][1]);
            *(float2*)(C + (size_t)(r + 8) * ldc + c) = make_float2(acc[t][u][2], acc[t][u][3]);
        }
    }
}

// ---------------- transpose + fp16 limb split ----------------
__global__ __launch_bounds__(256) void transpose_split(
    const float* __restrict__ in, __half* __restrict__ oh, __half* __restrict__ ol,
    int Kdim, int Ndim)
{
    __shared__ float t[32][33];
    int bx = blockIdx.x * 32, by = blockIdx.y * 32;
    int x = threadIdx.x, y = threadIdx.y;
#pragma unroll
    for (int i = 0; i < 32; i += 8)
        t[y + i][x] = in[(size_t)(by + y + i) * Ndim + bx + x];
    __syncthreads();
#pragma unroll
    for (int i = 0; i < 32; i += 8)
        wsplit(oh, ol, (size_t)(bx + y + i) * Kdim + by + x, t[x][y + i]);
}

// ---------------- fp16 limb split (no transpose) ----------------
__global__ __launch_bounds__(256) void split_kernel(
    const float* __restrict__ in, __half* __restrict__ oh, __half* __restrict__ ol, int n)
{
    int i = (blockIdx.x * 256 + threadIdx.x) * 4;
    if (i >= n) return;
    float4 v = *(const float4*)(in + i);
    wsplit(oh, ol, i,     v.x);
    wsplit(oh, ol, i + 1, v.y);
    wsplit(oh, ol, i + 2, v.z);
    wsplit(oh, ol, i + 3, v.w);
}

// ---------------- RoPE + reshape -> fp16 limbs ----------------
__global__ void rope_h(const float* __restrict__ qkv,
                       const float* __restrict__ cosb,
                       const float* __restrict__ sinb)
{
    int s = blockIdx.x, b = blockIdx.y;
    const float* row = qkv + (size_t)(b * Sc + s) * 3072;
    const float* cr  = cosb + (size_t)(b * Sc + s) * Dc;
    const float* sr  = sinb + (size_t)(b * Sc + s) * Dc;
    int t = threadIdx.x;

    for (int p = t; p < Hc * 64; p += 256) {            // q pairs
        int h = p >> 6, d = p & 63;
        float x1 = row[h * 128 + d], x2 = row[h * 128 + d + 64];
        size_t base = ((size_t)(b * Hc + h) * Sc + s) * Dc;
        wsplit(g_qh, g_ql, base + d,      x1 * cr[d]      - x2 * sr[d]);
        wsplit(g_qh, g_ql, base + d + 64, x2 * cr[d + 64] + x1 * sr[d + 64]);
    }
    for (int p = t; p < HKVc * 64; p += 256) {          // k pairs
        int h = p >> 6, d = p & 63;
        float x1 = row[2048 + h * 128 + d], x2 = row[2048 + h * 128 + d + 64];
        size_t base = ((size_t)(b * HKVc + h) * Sc + s) * Dc;
        wsplit(g_kh, g_kl, base + d,      x1 * cr[d]      - x2 * sr[d]);
        wsplit(g_kh, g_kl, base + d + 64, x2 * cr[d + 64] + x1 * sr[d + 64]);
    }
    for (int p = t; p < HKVc * Dc; p += 256) {          // v (hi only)
        int h = p >> 7, d = p & 127;
        size_t base = ((size_t)(b * HKVc + h) * Sc + s) * Dc;
        g_vh[base + d] = __float2half_rn(row[2560 + h * 128 + d]);
    }
}

// ---------------- block means over BS=64 rows (from limbs; fp32-grade) ----------------
__global__ void blockmean_h(const __half* __restrict__ xh, const __half* __restrict__ xl,
                            float* __restrict__ out, int HH)
{
    int i = blockIdx.x, h = blockIdx.y, b = blockIdx.z, d = threadIdx.x;
    size_t base = ((size_t)(b * HH + h) * Sc + i * BSc) * Dc + d;
    float sum = 0.f;
#pragma unroll
    for (int r = 0; r < BSc; r++) {
        size_t idx = base + (size_t)r * Dc;
        sum += __half2float(xh[idx]) + __half2float(xl[idx]);
    }
    out[((size_t)(b * HH + h) * NBc + i) * Dc + d] = sum * (1.0f / 64.0f);
}

// ---------------- gate mask ----------------
__global__ __launch_bounds__(1024) void mask_kernel()
{
    int bh = blockIdx.x;
    int b = bh / Hc, h = bh % Hc;
    int t = threadIdx.x;
    int i = t >> 5, j = t & 31;
    const float* qb = g_qblk + ((size_t)bh * NBc + i) * Dc;
    const float* kb = g_kblk + ((size_t)(b * HKVc + (h >> 2)) * NBc + j) * Dc;
    float dot = 0.f;
#pragma unroll 8
    for (int d = 0; d < Dc; d++) dot = fmaf(qb[d], kb[d], dot);
    bool hard = (dot * SCALEc >= 0.0f) || (i == j);
    hard = hard && (j <= i);
    unsigned bits = __ballot_sync(0xffffffffu, hard);
    if (j == 0) g_mask[(size_t)bh * NBc + i] = bits;
}

// ---------------- block-sparse flash attention, fp16 tensor cores ----------------
// CTA = (ib, h, b), 128 threads; warp w owns query rows 16w..16w+15.
// smem tiles Qh Ql Kh Vh: 64 rows x 128 halfs, row stride 272 B.
// QK = QhKh + QlKh (2 products); PV = P*Vh (1 product).
#define FSTRIDE 272
#define FTILE_B (64 * FSTRIDE)             // 17408 B
#define FLASH_SMEM (4 * FTILE_B)           // 69632 B

__global__ void __launch_bounds__(128, 3) flash_h()
{
    extern __shared__ char smc[];
    const uint32_t sb = smem_u32(smc);
    const uint32_t Qh = sb,               Ql = sb + FTILE_B;
    const uint32_t Kh = sb + 2 * FTILE_B, Vh = sb + 3 * FTILE_B;

    const int ib = blockIdx.x, h = blockIdx.y, b = blockIdx.z;
    const int tid = threadIdx.x, wid = tid >> 5, lane = tid & 31;
    const int g = lane >> 2, q = lane & 3;
    const int lrow = lane & 15;
    const uint32_t lcol = (uint32_t)(lane >> 4) * 16;

    const size_t qoff = ((size_t)(b * Hc + h) * Sc + (size_t)ib * 64) * Dc;
    const size_t koff = ((size_t)(b * HKVc + (h >> 2)) * Sc) * Dc;
    const unsigned maskrow = g_mask[(size_t)(b * Hc + h) * NBc + ib];

    // load Q limbs
    for (int slot = tid; slot < 1024; slot += 128) {
        int r = slot >> 4, s = slot & 15;
        int so = r * FSTRIDE + s * 16, go = r * 128 + s * 8;
        *(uint4*)(smc + so)           = *(const uint4*)(g_qh + qoff + go);
        *(uint4*)(smc + FTILE_B + so) = *(const uint4*)(g_ql + qoff + go);
    }

    float acc[16][4];
#pragma unroll
    for (int nt = 0; nt < 16; nt++)
#pragma unroll
        for (int c = 0; c < 4; c++) acc[nt][c] = 0.f;
    float m0 = -1e38f, m1 = -1e38f, l0 = 0.f, l1 = 0.f;
    __syncthreads();

    for (int jb = 0; jb <= ib; jb++) {
        if (!((maskrow >> jb) & 1u)) continue;
        const bool diag = (jb == ib);
        const size_t kvo = koff + (size_t)jb * 64 * Dc;

        for (int slot = tid; slot < 1024; slot += 128) {
            int r = slot >> 4, s = slot & 15;
            int so = r * FSTRIDE + s * 16, go = r * 128 + s * 8;
            *(uint4*)(smc + 2 * FTILE_B + so) = *(const uint4*)(g_kh + kvo + go);
            *(uint4*)(smc + 3 * FTILE_B + so) = *(const uint4*)(g_vh + kvo + go);
        }
        __syncthreads();

        // ---- QK^T (Q 2-limb x K hi) ----
        float s8[8][4];
#pragma unroll
        for (int nt = 0; nt < 8; nt++)
#pragma unroll
            for (int c = 0; c < 4; c++) s8[nt][c] = 0.f;

#pragma unroll
        for (int kb = 0; kb < 8; kb++) {
            const uint32_t ko = kb * 32 + lcol;
            uint32_t ah[4], al[4], bh[8][2], r4[4];
            ldm4(Qh + (16 * wid + lrow) * FSTRIDE + ko, ah);
            ldm4(Ql + (16 * wid + lrow) * FSTRIDE + ko, al);
#pragma unroll
            for (int p = 0; p < 4; p++) {
                ldm4(Kh + (p * 16 + lrow) * FSTRIDE + ko, r4);
                bh[2 * p][0] = r4[0]; bh[2 * p + 1][0] = r4[1];
                bh[2 * p][1] = r4[2]; bh[2 * p + 1][1] = r4[3];
            }
#pragma unroll
            for (int nt = 0; nt < 8; nt++) {
                MMA_F16(s8[nt], ah, bh[nt]);
                MMA_F16(s8[nt], al, bh[nt]);
            }
        }

        // ---- online softmax ----
        float mb0 = -1e38f, mb1 = -1e38f;
#pragma unroll
        for (int nt = 0; nt < 8; nt++)
#pragma unroll
            for (int c = 0; c < 4; c++) {
                float v = s8[nt][c] * SCALEc;
                if (diag) {
                    int col = nt * 8 + 2 * q + (c & 1);
                    int row = 16 * wid + g + (c >> 1) * 8;
                    if (col > row) v = -1e30f;
                }
                s8[nt][c] = v;
                if (c < 2) mb0 = fmaxf(mb0, v); else mb1 = fmaxf(mb1, v);
            }
        mb0 = fmaxf(mb0, __shfl_xor_sync(0xffffffffu, mb0, 1));
        mb0 = fmaxf(mb0, __shfl_xor_sync(0xffffffffu, mb0, 2));
        mb1 = fmaxf(mb1, __shfl_xor_sync(0xffffffffu, mb1, 1));
        mb1 = fmaxf(mb1, __shfl_xor_sync(0xffffffffu, mb1, 2));
        float mn0 = fmaxf(m0, mb0), mn1 = fmaxf(m1, mb1);
        float a0 = __expf(m0 - mn0), a1 = __expf(m1 - mn1);
        m0 = mn0; m1 = mn1;
        float ls0 = 0.f, ls1 = 0.f;
#pragma unroll
        for (int nt = 0; nt < 8; nt++) {
            float p0 = __expf(s8[nt][0] - mn0); s8[nt][0] = p0; ls0 += p0;
            float p1 = __expf(s8[nt][1] - mn0); s8[nt][1] = p1; ls0 += p1;
            float p2 = __expf(s8[nt][2] - mn1); s8[nt][2] = p2; ls1 += p2;
            float p3 = __expf(s8[nt][3] - mn1); s8[nt][3] = p3; ls1 += p3;
        }
        ls0 += __shfl_xor_sync(0xffffffffu, ls0, 1);
        ls0 += __shfl_xor_sync(0xffffffffu, ls0, 2);
        ls1 += __shfl_xor_sync(0xffffffffu, ls1, 1);
        ls1 += __shfl_xor_sync(0xffffffffu, ls1, 2);
        l0 = l0 * a0 + ls0;
        l1 = l1 * a1 + ls1;
#pragma unroll
        for (int nt = 0; nt < 16; nt++) {
            acc[nt][0] *= a0; acc[nt][1] *= a0;
            acc[nt][2] *= a1; acc[nt][3] *= a1;
        }

        // ---- P(fp16) @ V(hi) ----
        uint32_t pa[4][4];
#pragma unroll
        for (int kc = 0; kc < 4; kc++) {
            pa[kc][0] = packh2(s8[2 * kc][0],     s8[2 * kc][1]);
            pa[kc][1] = packh2(s8[2 * kc][2],     s8[2 * kc][3]);
            pa[kc][2] = packh2(s8[2 * kc + 1][0], s8[2 * kc + 1][1]);
            pa[kc][3] = packh2(s8[2 * kc + 1][2], s8[2 * kc + 1][3]);
        }
#pragma unroll
        for (int kc = 0; kc < 4; kc++) {
#pragma unroll
            for (int dp = 0; dp < 8; dp++) {
                uint32_t r4[4];
                ldm4t(Vh + (kc * 16 + lrow) * FSTRIDE + dp * 32 + lcol, r4);
                MMA_F16(acc[2 * dp],     pa[kc], r4);
                MMA_F16(acc[2 * dp + 1], pa[kc], r4 + 2);
            }
        }
        __syncthreads();   // K/V reads done before next iter's stores
    }

    // ---- epilogue: normalize, write hi-limb only (B,S,H*D) ----
    float inv0 = 1.f / l0, inv1 = 1.f / l1;
    size_t row0 = (size_t)b * Sc + (size_t)ib * 64 + 16 * wid + g;
#pragma unroll
    for (int nt = 0; nt < 16; nt++) {
        size_t off0 = row0 * 2048 + h * 128 + nt * 8 + 2 * q;
        size_t off1 = (row0 + 8) * 2048 + h * 128 + nt * 8 + 2 * q;
        *(__half2*)(g_ath + off0) = __floats2half2_rn(acc[nt][0] * inv0, acc[nt][1] * inv0);
        *(__half2*)(g_ath + off1) = __floats2half2_rn(acc[nt][2] * inv1, acc[nt][3] * inv1);
    }
}

// ---------------- launch ----------------
extern "C" void kernel_launch(void* const* d_in, const int* in_sizes, int n_in,
                              void* d_out, int out_size)
{
    const float* hidden = (const float*)d_in[0];
    const float* cosb   = (const float*)d_in[1];
    const float* sinb   = (const float*)d_in[2];
    const float* Wq     = (const float*)d_in[3];
    const float* Wk     = (const float*)d_in[4];
    const float* Wv     = (const float*)d_in[5];
    const float* Wo     = (const float*)d_in[6];
    float* out = (float*)d_out;

    float *qkv, *qblk, *kblk;
    __half *hh, *hl, *wth, *wtl, *woth, *wotl, *ath, *qh, *ql, *kh, *kl;
    cudaGetSymbolAddress((void**)&qkv,  g_qkv);
    cudaGetSymbolAddress((void**)&qblk, g_qblk);
    cudaGetSymbolAddress((void**)&kblk, g_kblk);
    cudaGetSymbolAddress((void**)&hh,   g_hh);
    cudaGetSymbolAddress((void**)&hl,   g_hl);
    cudaGetSymbolAddress((void**)&wth,  g_wth);
    cudaGetSymbolAddress((void**)&wtl,  g_wtl);
    cudaGetSymbolAddress((void**)&woth, g_woth);
    cudaGetSymbolAddress((void**)&wotl, g_wotl);
    cudaGetSymbolAddress((void**)&ath,  g_ath);
    cudaGetSymbolAddress((void**)&qh,   g_qh);
    cudaGetSymbolAddress((void**)&ql,   g_ql);
    cudaGetSymbolAddress((void**)&kh,   g_kh);
    cudaGetSymbolAddress((void**)&kl,   g_kl);

    // 0. weights -> transposed fp16 limbs; hidden -> fp16 limbs
    transpose_split<<<dim3(64, 64), dim3(32, 8)>>>(Wq, wth, wtl, 2048, 2048);
    transpose_split<<<dim3(16, 64), dim3(32, 8)>>>(Wk, wth + (size_t)2048 * 2048,
                                                       wtl + (size_t)2048 * 2048, 2048, 512);
    transpose_split<<<dim3(16, 64), dim3(32, 8)>>>(Wv, wth + (size_t)2560 * 2048,
                                                       wtl + (size_t)2560 * 2048, 2048, 512);
    transpose_split<<<dim3(64, 64), dim3(32, 8)>>>(Wo, woth, wotl, 2048, 2048);
    split_kernel<<<8192, 256>>>(hidden, hh, hl, 4096 * 2048);

    cudaFuncSetAttribute(gemm_h<3>, cudaFuncAttributeMaxDynamicSharedMemorySize, 3 * 4 * GTILE_B);
    cudaFuncSetAttribute(gemm_h<2>, cudaFuncAttributeMaxDynamicSharedMemorySize, 3 * 3 * GTILE_B);
    cudaFuncSetAttribute(gemm_h<1>, cudaFuncAttributeMaxDynamicSharedMemorySize, 3 * 2 * GTILE_B);

    // 1. QKV projection: q,k columns (mask-critical) 3-product; v columns 2-product
    gemm_h<3><<<dim3(20, 32), 256, 3 * 4 * GTILE_B>>>(hh, hl, wth, wtl, qkv, 3072, 2048);
    gemm_h<2><<<dim3(4, 32), 256, 3 * 3 * GTILE_B>>>(hh, hl,
        wth + (size_t)2560 * 2048, wtl + (size_t)2560 * 2048, qkv + 2560, 3072, 2048);

    // 2. RoPE -> fp16 limbs
    rope_h<<<dim3(Sc, Bc), 256>>>(qkv, cosb, sinb);

    // 3. block means (hi+lo; fp32-grade for the sign-critical mask)
    blockmean_h<<<dim3(NBc, Hc,   Bc), 128>>>(qh, ql, qblk, Hc);
    blockmean_h<<<dim3(NBc, HKVc, Bc), 128>>>(kh, kl, kblk, HKVc);

    // 4. gate bitmask
    mask_kernel<<<Bc * Hc, 1024>>>();

    // 5. block-sparse flash attention (fp16 tensor cores, trimmed limbs)
    cudaFuncSetAttribute(flash_h, cudaFuncAttributeMaxDynamicSharedMemorySize, FLASH_SMEM);
    flash_h<<<dim3(NBc, Hc, Bc), 128, FLASH_SMEM>>>();

    // 6. output projection: pure fp16 (1-product) — output-only error ~4.9e-4
    gemm_h<1><<<dim3(16, 32), 256, 3 * 2 * GTILE_B>>>(ath, ath, woth, woth, out, 2048, 2048);
}